// round 1
// baseline (speedup 1.0000x reference)
#include <cuda_runtime.h>

#define S_LEN   2048
#define EMBED   1024
#define E3      3072
#define HEADS   16
#define HDIM    64
#define BATCH   4
#define M_TOTAL (BATCH * S_LEN) /* 8192 */

// Scratch (allocation-free contract): qkv buffer + attention output buffer.
__device__ float g_qkv[(size_t)M_TOTAL * E3];   // ~100.7 MB
__device__ float g_attn[(size_t)M_TOTAL * EMBED]; // ~33.6 MB

// ---------------------------------------------------------------------------
// SGEMM: C[M,N] = A[M,K] @ B[K,N] + bias[N]
// 128x128 block tile, BK=8, 256 threads, 8x8 register tile per thread.
// ---------------------------------------------------------------------------
__global__ __launch_bounds__(256)
void sgemm_bias_kernel(const float* __restrict__ A, const float* __restrict__ B,
                       const float* __restrict__ bias, float* __restrict__ C,
                       int M, int N, int K) {
    __shared__ float As[8][132];   // transposed A tile, padded (132%4==0 keeps 16B align)
    __shared__ float Bs[8][128];

    const int tid = threadIdx.x;
    const int tx = tid & 15;
    const int ty = tid >> 4;
    const int row0 = blockIdx.y * 128;
    const int col0 = blockIdx.x * 128;

    // load assignments
    const int arow = tid >> 1;          // 0..127
    const int akq  = (tid & 1) * 4;     // 0 or 4
    const int bk   = tid >> 5;          // 0..7
    const int bn   = (tid & 31) * 4;    // 0..124

    const float* Aptr = A + (size_t)(row0 + arow) * K + akq;
    const float* Bptr = B + (size_t)bk * N + col0 + bn;

    float acc[8][8];
#pragma unroll
    for (int i = 0; i < 8; i++)
#pragma unroll
        for (int j = 0; j < 8; j++) acc[i][j] = 0.f;

    for (int k0 = 0; k0 < K; k0 += 8) {
        float4 av = *(const float4*)(Aptr + k0);
        float4 bv = *(const float4*)(Bptr + (size_t)k0 * N);
        As[akq + 0][arow] = av.x;
        As[akq + 1][arow] = av.y;
        As[akq + 2][arow] = av.z;
        As[akq + 3][arow] = av.w;
        *(float4*)&Bs[bk][bn] = bv;
        __syncthreads();

#pragma unroll
        for (int kk = 0; kk < 8; kk++) {
            float a[8], b[8];
            *(float4*)&a[0] = *(const float4*)&As[kk][ty * 8];
            *(float4*)&a[4] = *(const float4*)&As[kk][ty * 8 + 4];
            *(float4*)&b[0] = *(const float4*)&Bs[kk][tx * 8];
            *(float4*)&b[4] = *(const float4*)&Bs[kk][tx * 8 + 4];
#pragma unroll
            for (int i = 0; i < 8; i++)
#pragma unroll
                for (int j = 0; j < 8; j++)
                    acc[i][j] += a[i] * b[j];
        }
        __syncthreads();
    }

    float bvals[8];
#pragma unroll
    for (int j = 0; j < 8; j++) bvals[j] = bias[col0 + tx * 8 + j];

#pragma unroll
    for (int i = 0; i < 8; i++) {
        const size_t row = (size_t)(row0 + ty * 8 + i);
        float4 o0, o1;
        o0.x = acc[i][0] + bvals[0];
        o0.y = acc[i][1] + bvals[1];
        o0.z = acc[i][2] + bvals[2];
        o0.w = acc[i][3] + bvals[3];
        o1.x = acc[i][4] + bvals[4];
        o1.y = acc[i][5] + bvals[5];
        o1.z = acc[i][6] + bvals[6];
        o1.w = acc[i][7] + bvals[7];
        *(float4*)&C[row * N + col0 + tx * 8]     = o0;
        *(float4*)&C[row * N + col0 + tx * 8 + 4] = o1;
    }
}

// ---------------------------------------------------------------------------
// Flash attention: one CTA per (q-tile of 64, head, batch).
// Q resident in smem; stream 64-wide K/V tiles with online softmax.
// smem: Qs[64][65] + KPs[64][65] (K tile, later reused for P) + Vs[64][65].
// ---------------------------------------------------------------------------
__global__ __launch_bounds__(256)
void attn_kernel(const float* __restrict__ qkv, float* __restrict__ out) {
    extern __shared__ float sm[];
    float (*Qs)[65]  = (float (*)[65])sm;
    float (*KPs)[65] = (float (*)[65])(sm + 64 * 65);
    float (*Vs)[65]  = (float (*)[65])(sm + 2 * 64 * 65);

    const int tid = threadIdx.x;
    const int tx = tid & 15;
    const int ty = tid >> 4;
    const int qt = blockIdx.x;
    const int h  = blockIdx.y;
    const int b  = blockIdx.z;

    const size_t rowbase = (size_t)b * S_LEN;
    const size_t hoff    = (size_t)h * HDIM;

    // Load Q tile (vectorized gmem reads, scalar smem stores due to pad)
    {
        int idx = tid;
#pragma unroll
        for (int it = 0; it < 4; it++, idx += 256) {
            const int q  = idx >> 4;
            const int dq = (idx & 15) * 4;
            const float4 v = *(const float4*)&qkv[(rowbase + (size_t)(qt * 64 + q)) * E3 + hoff + dq];
            Qs[q][dq]     = v.x;
            Qs[q][dq + 1] = v.y;
            Qs[q][dq + 2] = v.z;
            Qs[q][dq + 3] = v.w;
        }
    }

    float m_old[4], l[4], acc[4][4];
#pragma unroll
    for (int i = 0; i < 4; i++) {
        m_old[i] = -1e30f;
        l[i] = 0.f;
#pragma unroll
        for (int j = 0; j < 4; j++) acc[i][j] = 0.f;
    }
    __syncthreads();

    for (int k0 = 0; k0 < S_LEN; k0 += 64) {
        // Load K and V tiles
        {
            int idx = tid;
#pragma unroll
            for (int it = 0; it < 4; it++, idx += 256) {
                const int kk = idx >> 4;
                const int dq = (idx & 15) * 4;
                const size_t g = (rowbase + (size_t)(k0 + kk)) * E3 + hoff + dq;
                const float4 kv = *(const float4*)&qkv[g + EMBED];
                const float4 vv = *(const float4*)&qkv[g + 2 * EMBED];
                KPs[kk][dq]     = kv.x;
                KPs[kk][dq + 1] = kv.y;
                KPs[kk][dq + 2] = kv.z;
                KPs[kk][dq + 3] = kv.w;
                Vs[kk][dq]     = vv.x;
                Vs[kk][dq + 1] = vv.y;
                Vs[kk][dq + 2] = vv.z;
                Vs[kk][dq + 3] = vv.w;
            }
        }
        __syncthreads();

        // S = Q @ K^T (per-thread 4x4)
        float s[4][4];
#pragma unroll
        for (int i = 0; i < 4; i++)
#pragma unroll
            for (int j = 0; j < 4; j++) s[i][j] = 0.f;

#pragma unroll 8
        for (int d = 0; d < 64; d++) {
            float a[4], bb[4];
#pragma unroll
            for (int i = 0; i < 4; i++) a[i]  = Qs[ty * 4 + i][d];
#pragma unroll
            for (int j = 0; j < 4; j++) bb[j] = KPs[tx * 4 + j][d];
#pragma unroll
            for (int i = 0; i < 4; i++)
#pragma unroll
                for (int j = 0; j < 4; j++)
                    s[i][j] += a[i] * bb[j];
        }
        __syncthreads();   // all K reads done before P overwrites KPs

        // Online softmax update. Row group = 16 lanes with same ty;
        // lane = (ty&1)*16 + tx, so xor shuffles of 1,2,4,8 reduce across tx.
#pragma unroll
        for (int i = 0; i < 4; i++) {
            float mx = -1e30f;
#pragma unroll
            for (int j = 0; j < 4; j++) {
                s[i][j] *= 0.125f;   // 1/sqrt(64)
                mx = fmaxf(mx, s[i][j]);
            }
#pragma unroll
            for (int o = 8; o > 0; o >>= 1)
                mx = fmaxf(mx, __shfl_xor_sync(0xffffffffu, mx, o));
            const float mnew = fmaxf(m_old[i], mx);
            float sum = 0.f;
#pragma unroll
            for (int j = 0; j < 4; j++) {
                const float p = __expf(s[i][j] - mnew);
                s[i][j] = p;
                sum += p;
            }
#pragma unroll
            for (int o = 8; o > 0; o >>= 1)
                sum += __shfl_xor_sync(0xffffffffu, sum, o);
            const float alpha = __expf(m_old[i] - mnew);
            l[i] = l[i] * alpha + sum;
#pragma unroll
            for (int j = 0; j < 4; j++) acc[i][j] *= alpha;
            m_old[i] = mnew;
        }

        // Write P into the K buffer
#pragma unroll
        for (int i = 0; i < 4; i++)
#pragma unroll
            for (int j = 0; j < 4; j++)
                KPs[ty * 4 + i][tx * 4 + j] = s[i][j];
        __syncthreads();

        // acc += P @ V
#pragma unroll 8
        for (int kk = 0; kk < 64; kk++) {
            float a[4], bb[4];
#pragma unroll
            for (int i = 0; i < 4; i++) a[i]  = KPs[ty * 4 + i][kk];
#pragma unroll
            for (int j = 0; j < 4; j++) bb[j] = Vs[kk][tx * 4 + j];
#pragma unroll
            for (int i = 0; i < 4; i++)
#pragma unroll
                for (int j = 0; j < 4; j++)
                    acc[i][j] += a[i] * bb[j];
        }
        __syncthreads();   // before next K/V tile overwrite
    }

    // Normalize and write attention output in [B,S,E] layout (heads interleaved)
#pragma unroll
    for (int i = 0; i < 4; i++) {
        const float inv = 1.f / l[i];
        const size_t q = (size_t)(qt * 64 + ty * 4 + i);
#pragma unroll
        for (int j = 0; j < 4; j++)
            out[(rowbase + q) * EMBED + hoff + tx * 4 + j] = acc[i][j] * inv;
    }
}

// ---------------------------------------------------------------------------
// Launch
// ---------------------------------------------------------------------------
extern "C" void kernel_launch(void* const* d_in, const int* in_sizes, int n_in,
                              void* d_out, int out_size) {
    const float* x     = (const float*)d_in[0];
    const float* W_qkv = (const float*)d_in[1];
    const float* b_qkv = (const float*)d_in[2];
    const float* W_out = (const float*)d_in[3];
    const float* b_out = (const float*)d_in[4];
    float* out = (float*)d_out;

    float *qkv_ptr, *attn_ptr;
    cudaGetSymbolAddress((void**)&qkv_ptr, g_qkv);
    cudaGetSymbolAddress((void**)&attn_ptr, g_attn);

    const int attn_smem = 3 * 64 * 65 * (int)sizeof(float); // 49,920 B
    cudaFuncSetAttribute(attn_kernel, cudaFuncAttributeMaxDynamicSharedMemorySize, attn_smem);

    // 1) QKV projection: [8192,1024] @ [1024,3072] + bias
    dim3 g1(E3 / 128, M_TOTAL / 128);
    sgemm_bias_kernel<<<g1, 256>>>(x, W_qkv, b_qkv, qkv_ptr, M_TOTAL, E3, EMBED);

    // 2) Attention
    dim3 g2(S_LEN / 64, HEADS, BATCH);
    attn_kernel<<<g2, 256, attn_smem>>>(qkv_ptr, attn_ptr);

    // 3) Output projection: [8192,1024] @ [1024,1024] + bias
    dim3 g3(EMBED / 128, M_TOTAL / 128);
    sgemm_bias_kernel<<<g3, 256>>>(attn_ptr, W_out, b_out, out, M_TOTAL, EMBED, EMBED);
}

// round 3
// speedup vs baseline: 1.3625x; 1.3625x over previous
#include <cuda_runtime.h>
#include <cuda_bf16.h>
#include <cstdint>

// ============================================================================
// Problem constants
// ============================================================================
#define S_LEN   2048
#define EMBED   1024
#define E3      3072
#define HEADS   16
#define HDIM    64
#define BATCH   4
#define M_TOTAL (BATCH * S_LEN) /* 8192 */

// Scratch (allocation-free contract)
__device__ float g_qkv[(size_t)M_TOTAL * E3];     // ~100.7 MB
__device__ float g_attn[(size_t)M_TOTAL * EMBED]; // ~33.6 MB
__device__ __align__(16) __nv_bfloat16 g_wq_hi[(size_t)E3 * EMBED];
__device__ __align__(16) __nv_bfloat16 g_wq_lo[(size_t)E3 * EMBED];
__device__ __align__(16) __nv_bfloat16 g_wo_hi[(size_t)EMBED * EMBED];
__device__ __align__(16) __nv_bfloat16 g_wo_lo[(size_t)EMBED * EMBED];

// ============================================================================
// Helpers
// ============================================================================
__device__ __forceinline__ uint32_t smem_to_u32(const void* smem_ptr) {
    uint32_t addr;
    asm("{ .reg .u64 tmp; cvta.to.shared.u64 tmp, %1; cvt.u32.u64 %0, tmp; }"
        : "=r"(addr) : "l"(smem_ptr));
    return addr;
}

#define SMEM_SWIZZLE_128B(byte_offset) \
    ((byte_offset) ^ (((byte_offset) >> 3) & 0x70))

__device__ __forceinline__ void ldsm4(uint32_t addr, uint32_t r[4]) {
    asm volatile("ldmatrix.sync.aligned.m8n8.x4.shared.b16 {%0,%1,%2,%3}, [%4];"
                 : "=r"(r[0]), "=r"(r[1]), "=r"(r[2]), "=r"(r[3]) : "r"(addr));
}

__device__ __forceinline__ void mma16816(float c[4], const uint32_t a[4],
                                         uint32_t b0, uint32_t b1) {
    asm volatile(
        "mma.sync.aligned.m16n8k16.row.col.f32.bf16.bf16.f32 "
        "{%0,%1,%2,%3}, {%4,%5,%6,%7}, {%8,%9}, {%0,%1,%2,%3};"
        : "+f"(c[0]), "+f"(c[1]), "+f"(c[2]), "+f"(c[3])
        : "r"(a[0]), "r"(a[1]), "r"(a[2]), "r"(a[3]), "r"(b0), "r"(b1));
}

__device__ __forceinline__ void split_bf16(float v, __nv_bfloat16& h, __nv_bfloat16& l) {
    h = __float2bfloat16(v);
    l = __float2bfloat16(v - __bfloat162float(h));
}

__device__ __forceinline__ uint32_t pack_bf16(__nv_bfloat16 a, __nv_bfloat16 b) {
    __nv_bfloat162 t = __halves2bfloat162(a, b);
    return *reinterpret_cast<uint32_t*>(&t);
}

// ============================================================================
// Prep: transpose W[K,N] -> Wt[N,K], split fp32 into bf16 hi + lo
// ============================================================================
__global__ __launch_bounds__(256)
void wtrans_split_kernel(const float* __restrict__ W, __nv_bfloat16* __restrict__ Th,
                         __nv_bfloat16* __restrict__ Tl, int K, int N) {
    __shared__ float t[32][33];
    const int n0 = blockIdx.x * 32, k0 = blockIdx.y * 32;
    const int tid = threadIdx.x;
    const int c = tid & 31, r = tid >> 5;
#pragma unroll
    for (int i = 0; i < 4; i++)
        t[r + i * 8][c] = W[(size_t)(k0 + r + i * 8) * N + n0 + c];
    __syncthreads();
    const int n  = tid >> 3;
    const int kq = (tid & 7) * 4;
    __nv_bfloat16 h[4], l[4];
#pragma unroll
    for (int j = 0; j < 4; j++) split_bf16(t[kq + j][n], h[j], l[j]);
    const size_t o = (size_t)(n0 + n) * K + k0 + kq;
    *(__nv_bfloat162*)&Th[o]     = __halves2bfloat162(h[0], h[1]);
    *(__nv_bfloat162*)&Th[o + 2] = __halves2bfloat162(h[2], h[3]);
    *(__nv_bfloat162*)&Tl[o]     = __halves2bfloat162(l[0], l[1]);
    *(__nv_bfloat162*)&Tl[o + 2] = __halves2bfloat162(l[2], l[3]);
}

// ============================================================================
// HMMA GEMM: C[M,N] = A[M,K](fp32) @ Bt[N,K](bf16 hi/lo, K-major) + bias
// 3x bf16-split (AhBh + AhBl + AlBh), fp32 register accumulators.
// CTA 128x128, 8 warps (2x4), warp tile 64x32, BK=64, double-buffered smem.
// ============================================================================
#define BM 128
#define BN 128
#define BK 64
#define TILE_SZ   16384               /* 128 rows x 128 B (64 bf16) SW128 */
#define STAGE_SZ  (4 * TILE_SZ)       /* Ah Al Bh Bl */
#define SM_GEMM_TOTAL (2 * STAGE_SZ)  /* 131072 B dynamic */

__global__ __launch_bounds__(256, 1)
void tc_gemm_bias(const float* __restrict__ A, const __nv_bfloat16* __restrict__ Bth,
                  const __nv_bfloat16* __restrict__ Btl, const float* __restrict__ bias,
                  float* __restrict__ C, int M, int N, int K) {
    extern __shared__ char smem[];
    __shared__ float sbias[BN];
    const uint32_t sb = smem_to_u32(smem);
    const int tid  = threadIdx.x;
    const int wid  = tid >> 5;
    const int lane = tid & 31;
    const int row0 = blockIdx.y * BM;
    const int col0 = blockIdx.x * BN;
    const int nchunks = K / BK;

    if (tid < BN) sbias[tid] = bias[col0 + tid];

    // ---- producer assignments ----
    const int a_kq = (tid & 15) * 4;   // fp32 col within chunk (0..60)
    const int a_m0 = tid >> 4;         // rows a_m0 + 16*i
    const int b_kg = (tid & 7) * 8;    // bf16 col group (0..56)
    const int b_n0 = tid >> 3;         // rows b_n0 + 32*i

    // per-thread swizzled smem store offsets
    uint32_t a_soff[8], b_soff[4];
#pragma unroll
    for (int i = 0; i < 8; i++) {
        const int m = a_m0 + i * 16;
        a_soff[i] = SMEM_SWIZZLE_128B((uint32_t)(m * 128 + a_kq * 2));
    }
#pragma unroll
    for (int i = 0; i < 4; i++) {
        const int n = b_n0 + i * 32;
        b_soff[i] = SMEM_SWIZZLE_128B((uint32_t)(n * 128 + b_kg * 2));
    }

    // ---- consumer (ldmatrix) per-thread address components ----
    const int wm = (wid >> 2) * 64;   // warp m offset
    const int wn = (wid & 3) * 32;    // warp n offset
    const int a_r    = lane & 15;
    const int a_half = lane >> 4;
    const int b_nr   = (lane & 7) | ((lane >> 4) << 3);
    const int b_kh   = (lane >> 3) & 1;

    uint32_t a_rowoff[4], a_xor[4], b_rowoff[2], b_xor[2];
#pragma unroll
    for (int i = 0; i < 4; i++) {
        const int r = wm + i * 16 + a_r;
        a_rowoff[i] = (uint32_t)(r * 128);
        a_xor[i]    = (uint32_t)((r & 7) << 4);
    }
#pragma unroll
    for (int jp = 0; jp < 2; jp++) {
        const int r = wn + jp * 16 + b_nr;
        b_rowoff[jp] = (uint32_t)(r * 128);
        b_xor[jp]    = (uint32_t)((r & 7) << 4);
    }
    const uint32_t a_kbb = (uint32_t)(a_half * 16);
    const uint32_t b_kbb = (uint32_t)(b_kh * 16);

    float acc[4][4][4];
#pragma unroll
    for (int i = 0; i < 4; i++)
#pragma unroll
        for (int j = 0; j < 4; j++)
#pragma unroll
            for (int q = 0; q < 4; q++) acc[i][j][q] = 0.f;

    // ---- preload chunk 0 into stage 0 ----
    {
        const uint32_t st = sb;
#pragma unroll
        for (int i = 0; i < 8; i++) {
            const int m = a_m0 + i * 16;
            const float4 v = *(const float4*)&A[(size_t)(row0 + m) * K + a_kq];
            __nv_bfloat16 h0, h1, h2, h3, l0, l1, l2, l3;
            split_bf16(v.x, h0, l0); split_bf16(v.y, h1, l1);
            split_bf16(v.z, h2, l2); split_bf16(v.w, h3, l3);
            asm volatile("st.shared.v2.b32 [%0], {%1, %2};"
                :: "r"(st + a_soff[i]), "r"(pack_bf16(h0, h1)), "r"(pack_bf16(h2, h3)) : "memory");
            asm volatile("st.shared.v2.b32 [%0], {%1, %2};"
                :: "r"(st + TILE_SZ + a_soff[i]), "r"(pack_bf16(l0, l1)), "r"(pack_bf16(l2, l3)) : "memory");
        }
#pragma unroll
        for (int i = 0; i < 4; i++) {
            const int n = b_n0 + i * 32;
            const size_t g = (size_t)(col0 + n) * K + b_kg;
            const uint4 vh = *(const uint4*)&Bth[g];
            const uint4 vl = *(const uint4*)&Btl[g];
            asm volatile("st.shared.v4.b32 [%0], {%1, %2, %3, %4};"
                :: "r"(st + 2 * TILE_SZ + b_soff[i]), "r"(vh.x), "r"(vh.y), "r"(vh.z), "r"(vh.w) : "memory");
            asm volatile("st.shared.v4.b32 [%0], {%1, %2, %3, %4};"
                :: "r"(st + 3 * TILE_SZ + b_soff[i]), "r"(vl.x), "r"(vl.y), "r"(vl.z), "r"(vl.w) : "memory");
        }
    }
    __syncthreads();

    for (int c = 0; c < nchunks; c++) {
        const uint32_t st = sb + (uint32_t)(c & 1) * STAGE_SZ;

        // prefetch next chunk's gmem into registers (overlaps MMA below)
        float4 pa[8];
        uint4 pbh[4], pbl[4];
        const bool more = (c + 1 < nchunks);
        if (more) {
            const int k0n = (c + 1) * BK;
#pragma unroll
            for (int i = 0; i < 8; i++) {
                const int m = a_m0 + i * 16;
                pa[i] = *(const float4*)&A[(size_t)(row0 + m) * K + k0n + a_kq];
            }
#pragma unroll
            for (int i = 0; i < 4; i++) {
                const int n = b_n0 + i * 32;
                const size_t g = (size_t)(col0 + n) * K + k0n + b_kg;
                pbh[i] = *(const uint4*)&Bth[g];
                pbl[i] = *(const uint4*)&Btl[g];
            }
        }

        // ---- consume: 4 k-steps of m16n8k16 ----
        const uint32_t stAh = st, stAl = st + TILE_SZ;
        const uint32_t stBh = st + 2 * TILE_SZ, stBl = st + 3 * TILE_SZ;
#pragma unroll
        for (int ks = 0; ks < 4; ks++) {
            const uint32_t kbA = (uint32_t)(ks * 32) + a_kbb;
            const uint32_t kbB = (uint32_t)(ks * 32) + b_kbb;
            uint32_t ah[4][4], al[4][4], bh[2][4], bl[2][4];
#pragma unroll
            for (int i = 0; i < 4; i++) {
                ldsm4(stAh + a_rowoff[i] + (kbA ^ a_xor[i]), ah[i]);
                ldsm4(stAl + a_rowoff[i] + (kbA ^ a_xor[i]), al[i]);
            }
#pragma unroll
            for (int jp = 0; jp < 2; jp++) {
                ldsm4(stBh + b_rowoff[jp] + (kbB ^ b_xor[jp]), bh[jp]);
                ldsm4(stBl + b_rowoff[jp] + (kbB ^ b_xor[jp]), bl[jp]);
            }
            // term 1: Ah*Bh
#pragma unroll
            for (int i = 0; i < 4; i++)
#pragma unroll
                for (int j = 0; j < 4; j++)
                    mma16816(acc[i][j], ah[i], bh[j >> 1][(j & 1) * 2], bh[j >> 1][(j & 1) * 2 + 1]);
            // term 2: Ah*Bl
#pragma unroll
            for (int i = 0; i < 4; i++)
#pragma unroll
                for (int j = 0; j < 4; j++)
                    mma16816(acc[i][j], ah[i], bl[j >> 1][(j & 1) * 2], bl[j >> 1][(j & 1) * 2 + 1]);
            // term 3: Al*Bh
#pragma unroll
            for (int i = 0; i < 4; i++)
#pragma unroll
                for (int j = 0; j < 4; j++)
                    mma16816(acc[i][j], al[i], bh[j >> 1][(j & 1) * 2], bh[j >> 1][(j & 1) * 2 + 1]);
        }
        __syncthreads();

        if (more) {
            const uint32_t stn = sb + (uint32_t)((c + 1) & 1) * STAGE_SZ;
#pragma unroll
            for (int i = 0; i < 8; i++) {
                __nv_bfloat16 h0, h1, h2, h3, l0, l1, l2, l3;
                split_bf16(pa[i].x, h0, l0); split_bf16(pa[i].y, h1, l1);
                split_bf16(pa[i].z, h2, l2); split_bf16(pa[i].w, h3, l3);
                asm volatile("st.shared.v2.b32 [%0], {%1, %2};"
                    :: "r"(stn + a_soff[i]), "r"(pack_bf16(h0, h1)), "r"(pack_bf16(h2, h3)) : "memory");
                asm volatile("st.shared.v2.b32 [%0], {%1, %2};"
                    :: "r"(stn + TILE_SZ + a_soff[i]), "r"(pack_bf16(l0, l1)), "r"(pack_bf16(l2, l3)) : "memory");
            }
#pragma unroll
            for (int i = 0; i < 4; i++) {
                asm volatile("st.shared.v4.b32 [%0], {%1, %2, %3, %4};"
                    :: "r"(stn + 2 * TILE_SZ + b_soff[i]), "r"(pbh[i].x), "r"(pbh[i].y), "r"(pbh[i].z), "r"(pbh[i].w) : "memory");
                asm volatile("st.shared.v4.b32 [%0], {%1, %2, %3, %4};"
                    :: "r"(stn + 3 * TILE_SZ + b_soff[i]), "r"(pbl[i].x), "r"(pbl[i].y), "r"(pbl[i].z), "r"(pbl[i].w) : "memory");
            }
            __syncthreads();
        }
    }

    // ---- epilogue: register accs + bias -> C ----
    const int cr  = lane >> 2;
    const int cc2 = (lane & 3) * 2;
#pragma unroll
    for (int i = 0; i < 4; i++) {
#pragma unroll
        for (int j = 0; j < 4; j++) {
            const int col = wn + j * 8 + cc2;
            const float b0 = sbias[col], b1 = sbias[col + 1];
            const int r0 = row0 + wm + i * 16 + cr;
            float2 o0 = make_float2(acc[i][j][0] + b0, acc[i][j][1] + b1);
            float2 o1 = make_float2(acc[i][j][2] + b0, acc[i][j][3] + b1);
            *(float2*)&C[(size_t)r0 * N + col0 + col]       = o0;
            *(float2*)&C[(size_t)(r0 + 8) * N + col0 + col] = o1;
        }
    }
}

// ============================================================================
// Flash attention (fp32 SIMT) — unchanged, verified in round 1
// ============================================================================
__global__ __launch_bounds__(256)
void attn_kernel(const float* __restrict__ qkv, float* __restrict__ out) {
    extern __shared__ float sm[];
    float (*Qs)[65]  = (float (*)[65])sm;
    float (*KPs)[65] = (float (*)[65])(sm + 64 * 65);
    float (*Vs)[65]  = (float (*)[65])(sm + 2 * 64 * 65);

    const int tid = threadIdx.x;
    const int tx = tid & 15;
    const int ty = tid >> 4;
    const int qt = blockIdx.x;
    const int h  = blockIdx.y;
    const int b  = blockIdx.z;

    const size_t rowbase = (size_t)b * S_LEN;
    const size_t hoff    = (size_t)h * HDIM;

    {
        int idx = tid;
#pragma unroll
        for (int it = 0; it < 4; it++, idx += 256) {
            const int q  = idx >> 4;
            const int dq = (idx & 15) * 4;
            const float4 v = *(const float4*)&qkv[(rowbase + (size_t)(qt * 64 + q)) * E3 + hoff + dq];
            Qs[q][dq]     = v.x;
            Qs[q][dq + 1] = v.y;
            Qs[q][dq + 2] = v.z;
            Qs[q][dq + 3] = v.w;
        }
    }

    float m_old[4], l[4], acc[4][4];
#pragma unroll
    for (int i = 0; i < 4; i++) {
        m_old[i] = -1e30f;
        l[i] = 0.f;
#pragma unroll
        for (int j = 0; j < 4; j++) acc[i][j] = 0.f;
    }
    __syncthreads();

    for (int k0 = 0; k0 < S_LEN; k0 += 64) {
        {
            int idx = tid;
#pragma unroll
            for (int it = 0; it < 4; it++, idx += 256) {
                const int kk = idx >> 4;
                const int dq = (idx & 15) * 4;
                const size_t g = (rowbase + (size_t)(k0 + kk)) * E3 + hoff + dq;
                const float4 kv = *(const float4*)&qkv[g + EMBED];
                const float4 vv = *(const float4*)&qkv[g + 2 * EMBED];
                KPs[kk][dq]     = kv.x;
                KPs[kk][dq + 1] = kv.y;
                KPs[kk][dq + 2] = kv.z;
                KPs[kk][dq + 3] = kv.w;
                Vs[kk][dq]     = vv.x;
                Vs[kk][dq + 1] = vv.y;
                Vs[kk][dq + 2] = vv.z;
                Vs[kk][dq + 3] = vv.w;
            }
        }
        __syncthreads();

        float s[4][4];
#pragma unroll
        for (int i = 0; i < 4; i++)
#pragma unroll
            for (int j = 0; j < 4; j++) s[i][j] = 0.f;

#pragma unroll 8
        for (int d = 0; d < 64; d++) {
            float a[4], bb[4];
#pragma unroll
            for (int i = 0; i < 4; i++) a[i]  = Qs[ty * 4 + i][d];
#pragma unroll
            for (int j = 0; j < 4; j++) bb[j] = KPs[tx * 4 + j][d];
#pragma unroll
            for (int i = 0; i < 4; i++)
#pragma unroll
                for (int j = 0; j < 4; j++)
                    s[i][j] += a[i] * bb[j];
        }
        __syncthreads();

#pragma unroll
        for (int i = 0; i < 4; i++) {
            float mx = -1e30f;
#pragma unroll
            for (int j = 0; j < 4; j++) {
                s[i][j] *= 0.125f;
                mx = fmaxf(mx, s[i][j]);
            }
#pragma unroll
            for (int o = 8; o > 0; o >>= 1)
                mx = fmaxf(mx, __shfl_xor_sync(0xffffffffu, mx, o));
            const float mnew = fmaxf(m_old[i], mx);
            float sum = 0.f;
#pragma unroll
            for (int j = 0; j < 4; j++) {
                const float p = __expf(s[i][j] - mnew);
                s[i][j] = p;
                sum += p;
            }
#pragma unroll
            for (int o = 8; o > 0; o >>= 1)
                sum += __shfl_xor_sync(0xffffffffu, sum, o);
            const float alpha = __expf(m_old[i] - mnew);
            l[i] = l[i] * alpha + sum;
#pragma unroll
            for (int j = 0; j < 4; j++) acc[i][j] *= alpha;
            m_old[i] = mnew;
        }

#pragma unroll
        for (int i = 0; i < 4; i++)
#pragma unroll
            for (int j = 0; j < 4; j++)
                KPs[ty * 4 + i][tx * 4 + j] = s[i][j];
        __syncthreads();

#pragma unroll 8
        for (int kk = 0; kk < 64; kk++) {
            float a[4], bb[4];
#pragma unroll
            for (int i = 0; i < 4; i++) a[i]  = KPs[ty * 4 + i][kk];
#pragma unroll
            for (int j = 0; j < 4; j++) bb[j] = Vs[kk][tx * 4 + j];
#pragma unroll
            for (int i = 0; i < 4; i++)
#pragma unroll
                for (int j = 0; j < 4; j++)
                    acc[i][j] += a[i] * bb[j];
        }
        __syncthreads();
    }

#pragma unroll
    for (int i = 0; i < 4; i++) {
        const float inv = 1.f / l[i];
        const size_t q = (size_t)(qt * 64 + ty * 4 + i);
#pragma unroll
        for (int j = 0; j < 4; j++)
            out[(rowbase + q) * EMBED + hoff + tx * 4 + j] = acc[i][j] * inv;
    }
}

// ============================================================================
// Launch
// ============================================================================
extern "C" void kernel_launch(void* const* d_in, const int* in_sizes, int n_in,
                              void* d_out, int out_size) {
    const float* x     = (const float*)d_in[0];
    const float* W_qkv = (const float*)d_in[1];
    const float* b_qkv = (const float*)d_in[2];
    const float* W_out = (const float*)d_in[3];
    const float* b_out = (const float*)d_in[4];
    float* out = (float*)d_out;

    float *qkv_ptr, *attn_ptr;
    cudaGetSymbolAddress((void**)&qkv_ptr, g_qkv);
    cudaGetSymbolAddress((void**)&attn_ptr, g_attn);
    __nv_bfloat16 *wq_hi, *wq_lo, *wo_hi, *wo_lo;
    cudaGetSymbolAddress((void**)&wq_hi, g_wq_hi);
    cudaGetSymbolAddress((void**)&wq_lo, g_wq_lo);
    cudaGetSymbolAddress((void**)&wo_hi, g_wo_hi);
    cudaGetSymbolAddress((void**)&wo_lo, g_wo_lo);

    const int attn_smem = 3 * 64 * 65 * (int)sizeof(float);
    cudaFuncSetAttribute(attn_kernel, cudaFuncAttributeMaxDynamicSharedMemorySize, attn_smem);
    cudaFuncSetAttribute(tc_gemm_bias, cudaFuncAttributeMaxDynamicSharedMemorySize, SM_GEMM_TOTAL);

    // 0) weight transpose + bf16 split
    wtrans_split_kernel<<<dim3(E3 / 32, EMBED / 32), 256>>>(W_qkv, wq_hi, wq_lo, EMBED, E3);
    wtrans_split_kernel<<<dim3(EMBED / 32, EMBED / 32), 256>>>(W_out, wo_hi, wo_lo, EMBED, EMBED);

    // 1) QKV projection (HMMA)
    tc_gemm_bias<<<dim3(E3 / BN, M_TOTAL / BM), 256, SM_GEMM_TOTAL>>>(
        x, wq_hi, wq_lo, b_qkv, qkv_ptr, M_TOTAL, E3, EMBED);

    // 2) Attention (fp32 SIMT, unchanged)
    dim3 g2(S_LEN / 64, HEADS, BATCH);
    attn_kernel<<<g2, 256, attn_smem>>>(qkv_ptr, attn_ptr);

    // 3) Output projection (HMMA)
    tc_gemm_bias<<<dim3(EMBED / BN, M_TOTAL / BM), 256, SM_GEMM_TOTAL>>>(
        attn_ptr, wo_hi, wo_lo, b_out, out, M_TOTAL, EMBED, EMBED);
}

// round 4
// speedup vs baseline: 3.0910x; 2.2685x over previous
#include <cuda_runtime.h>
#include <cuda_bf16.h>
#include <cstdint>

// ============================================================================
// Problem constants
// ============================================================================
#define S_LEN   2048
#define EMBED   1024
#define E3      3072
#define HEADS   16
#define HDIM    64
#define BATCH   4
#define M_TOTAL (BATCH * S_LEN) /* 8192 */

// Scratch (allocation-free contract)
__device__ __align__(16) __nv_bfloat16 g_qkvh[(size_t)M_TOTAL * E3]; // ~50MB
__device__ __align__(16) __nv_bfloat16 g_qkvl[(size_t)M_TOTAL * E3]; // ~50MB
__device__ float g_attn[(size_t)M_TOTAL * EMBED];                    // ~33.6 MB
__device__ __align__(16) __nv_bfloat16 g_wq_hi[(size_t)E3 * EMBED];
__device__ __align__(16) __nv_bfloat16 g_wq_lo[(size_t)E3 * EMBED];
__device__ __align__(16) __nv_bfloat16 g_wo_hi[(size_t)EMBED * EMBED];
__device__ __align__(16) __nv_bfloat16 g_wo_lo[(size_t)EMBED * EMBED];

// ============================================================================
// Helpers
// ============================================================================
__device__ __forceinline__ uint32_t smem_to_u32(const void* smem_ptr) {
    uint32_t addr;
    asm("{ .reg .u64 tmp; cvta.to.shared.u64 tmp, %1; cvt.u32.u64 %0, tmp; }"
        : "=r"(addr) : "l"(smem_ptr));
    return addr;
}

#define SMEM_SWIZZLE_128B(byte_offset) \
    ((byte_offset) ^ (((byte_offset) >> 3) & 0x70))

__device__ __forceinline__ void ldsm4(uint32_t addr, uint32_t r[4]) {
    asm volatile("ldmatrix.sync.aligned.m8n8.x4.shared.b16 {%0,%1,%2,%3}, [%4];"
                 : "=r"(r[0]), "=r"(r[1]), "=r"(r[2]), "=r"(r[3]) : "r"(addr));
}

__device__ __forceinline__ void ldsm4t(uint32_t addr, uint32_t r[4]) {
    asm volatile("ldmatrix.sync.aligned.m8n8.x4.trans.shared.b16 {%0,%1,%2,%3}, [%4];"
                 : "=r"(r[0]), "=r"(r[1]), "=r"(r[2]), "=r"(r[3]) : "r"(addr));
}

__device__ __forceinline__ void mma16816(float c[4], const uint32_t a[4],
                                         uint32_t b0, uint32_t b1) {
    asm volatile(
        "mma.sync.aligned.m16n8k16.row.col.f32.bf16.bf16.f32 "
        "{%0,%1,%2,%3}, {%4,%5,%6,%7}, {%8,%9}, {%0,%1,%2,%3};"
        : "+f"(c[0]), "+f"(c[1]), "+f"(c[2]), "+f"(c[3])
        : "r"(a[0]), "r"(a[1]), "r"(a[2]), "r"(a[3]), "r"(b0), "r"(b1));
}

__device__ __forceinline__ void cp_async16(uint32_t saddr, const void* gptr) {
    asm volatile("cp.async.cg.shared.global [%0], [%1], 16;"
                 :: "r"(saddr), "l"(gptr) : "memory");
}
#define CP_COMMIT() asm volatile("cp.async.commit_group;" ::: "memory")

__device__ __forceinline__ void split_bf16(float v, __nv_bfloat16& h, __nv_bfloat16& l) {
    h = __float2bfloat16(v);
    l = __float2bfloat16(v - __bfloat162float(h));
}

__device__ __forceinline__ uint32_t pack_bf16(__nv_bfloat16 a, __nv_bfloat16 b) {
    __nv_bfloat162 t = __halves2bfloat162(a, b);
    return *reinterpret_cast<uint32_t*>(&t);
}

// pack (x,y) -> bf16x2 hi-word, and the residual pair -> lo-word
__device__ __forceinline__ void pack_split(float x, float y, uint32_t& hp, uint32_t& lp) {
    asm("cvt.rn.bf16x2.f32 %0, %1, %2;" : "=r"(hp) : "f"(y), "f"(x)); // lo=x, hi=y
    const float hx = __uint_as_float(hp << 16);
    const float hy = __uint_as_float(hp & 0xffff0000u);
    const float rx = x - hx, ry = y - hy;
    asm("cvt.rn.bf16x2.f32 %0, %1, %2;" : "=r"(lp) : "f"(ry), "f"(rx));
}

// ============================================================================
// Prep: transpose W[K,N] -> Wt[N,K], split fp32 into bf16 hi + lo
// ============================================================================
__global__ __launch_bounds__(256)
void wtrans_split_kernel(const float* __restrict__ W, __nv_bfloat16* __restrict__ Th,
                         __nv_bfloat16* __restrict__ Tl, int K, int N) {
    __shared__ float t[32][33];
    const int n0 = blockIdx.x * 32, k0 = blockIdx.y * 32;
    const int tid = threadIdx.x;
    const int c = tid & 31, r = tid >> 5;
#pragma unroll
    for (int i = 0; i < 4; i++)
        t[r + i * 8][c] = W[(size_t)(k0 + r + i * 8) * N + n0 + c];
    __syncthreads();
    const int n  = tid >> 3;
    const int kq = (tid & 7) * 4;
    __nv_bfloat16 h[4], l[4];
#pragma unroll
    for (int j = 0; j < 4; j++) split_bf16(t[kq + j][n], h[j], l[j]);
    const size_t o = (size_t)(n0 + n) * K + k0 + kq;
    *(__nv_bfloat162*)&Th[o]     = __halves2bfloat162(h[0], h[1]);
    *(__nv_bfloat162*)&Th[o + 2] = __halves2bfloat162(h[2], h[3]);
    *(__nv_bfloat162*)&Tl[o]     = __halves2bfloat162(l[0], l[1]);
    *(__nv_bfloat162*)&Tl[o + 2] = __halves2bfloat162(l[2], l[3]);
}

// ============================================================================
// HMMA GEMM: C = A[M,K](fp32) @ Bt[N,K](bf16 hi/lo) + bias
// Output either fp32 (Cf) or pre-split bf16 hi/lo (Ch/Cl), with optional
// 0.125 scaling of columns < scale_cols (exact power of two).
// ============================================================================
#define BM 128
#define BN 128
#define BK 64
#define TILE_SZ   16384
#define STAGE_SZ  (4 * TILE_SZ)
#define SM_GEMM_TOTAL (2 * STAGE_SZ)

__global__ __launch_bounds__(256, 1)
void tc_gemm_bias(const float* __restrict__ A, const __nv_bfloat16* __restrict__ Bth,
                  const __nv_bfloat16* __restrict__ Btl, const float* __restrict__ bias,
                  float* __restrict__ Cf, __nv_bfloat16* __restrict__ Ch,
                  __nv_bfloat16* __restrict__ Cl,
                  int M, int N, int K, int scale_cols) {
    extern __shared__ char smem[];
    __shared__ float sbias[BN];
    const uint32_t sb = smem_to_u32(smem);
    const int tid  = threadIdx.x;
    const int wid  = tid >> 5;
    const int lane = tid & 31;
    const int row0 = blockIdx.y * BM;
    const int col0 = blockIdx.x * BN;
    const int nchunks = K / BK;

    if (tid < BN) sbias[tid] = bias[col0 + tid];

    const int a_kq = (tid & 15) * 4;
    const int a_m0 = tid >> 4;
    const int b_kg = (tid & 7) * 8;
    const int b_n0 = tid >> 3;

    uint32_t a_soff[8], b_soff[4];
#pragma unroll
    for (int i = 0; i < 8; i++) {
        const int m = a_m0 + i * 16;
        a_soff[i] = SMEM_SWIZZLE_128B((uint32_t)(m * 128 + a_kq * 2));
    }
#pragma unroll
    for (int i = 0; i < 4; i++) {
        const int n = b_n0 + i * 32;
        b_soff[i] = SMEM_SWIZZLE_128B((uint32_t)(n * 128 + b_kg * 2));
    }

    const int wm = (wid >> 2) * 64;
    const int wn = (wid & 3) * 32;
    const int a_r    = lane & 15;
    const int a_half = lane >> 4;
    const int b_nr   = (lane & 7) | ((lane >> 4) << 3);
    const int b_kh   = (lane >> 3) & 1;

    uint32_t a_rowoff[4], a_xor[4], b_rowoff[2], b_xor[2];
#pragma unroll
    for (int i = 0; i < 4; i++) {
        const int r = wm + i * 16 + a_r;
        a_rowoff[i] = (uint32_t)(r * 128);
        a_xor[i]    = (uint32_t)((r & 7) << 4);
    }
#pragma unroll
    for (int jp = 0; jp < 2; jp++) {
        const int r = wn + jp * 16 + b_nr;
        b_rowoff[jp] = (uint32_t)(r * 128);
        b_xor[jp]    = (uint32_t)((r & 7) << 4);
    }
    const uint32_t a_kbb = (uint32_t)(a_half * 16);
    const uint32_t b_kbb = (uint32_t)(b_kh * 16);

    float acc[4][4][4];
#pragma unroll
    for (int i = 0; i < 4; i++)
#pragma unroll
        for (int j = 0; j < 4; j++)
#pragma unroll
            for (int q = 0; q < 4; q++) acc[i][j][q] = 0.f;

    {
        const uint32_t st = sb;
#pragma unroll
        for (int i = 0; i < 8; i++) {
            const int m = a_m0 + i * 16;
            const float4 v = *(const float4*)&A[(size_t)(row0 + m) * K + a_kq];
            __nv_bfloat16 h0, h1, h2, h3, l0, l1, l2, l3;
            split_bf16(v.x, h0, l0); split_bf16(v.y, h1, l1);
            split_bf16(v.z, h2, l2); split_bf16(v.w, h3, l3);
            asm volatile("st.shared.v2.b32 [%0], {%1, %2};"
                :: "r"(st + a_soff[i]), "r"(pack_bf16(h0, h1)), "r"(pack_bf16(h2, h3)) : "memory");
            asm volatile("st.shared.v2.b32 [%0], {%1, %2};"
                :: "r"(st + TILE_SZ + a_soff[i]), "r"(pack_bf16(l0, l1)), "r"(pack_bf16(l2, l3)) : "memory");
        }
#pragma unroll
        for (int i = 0; i < 4; i++) {
            const int n = b_n0 + i * 32;
            const size_t g = (size_t)(col0 + n) * K + b_kg;
            const uint4 vh = *(const uint4*)&Bth[g];
            const uint4 vl = *(const uint4*)&Btl[g];
            asm volatile("st.shared.v4.b32 [%0], {%1, %2, %3, %4};"
                :: "r"(st + 2 * TILE_SZ + b_soff[i]), "r"(vh.x), "r"(vh.y), "r"(vh.z), "r"(vh.w) : "memory");
            asm volatile("st.shared.v4.b32 [%0], {%1, %2, %3, %4};"
                :: "r"(st + 3 * TILE_SZ + b_soff[i]), "r"(vl.x), "r"(vl.y), "r"(vl.z), "r"(vl.w) : "memory");
        }
    }
    __syncthreads();

    for (int c = 0; c < nchunks; c++) {
        const uint32_t st = sb + (uint32_t)(c & 1) * STAGE_SZ;

        float4 pa[8];
        uint4 pbh[4], pbl[4];
        const bool more = (c + 1 < nchunks);
        if (more) {
            const int k0n = (c + 1) * BK;
#pragma unroll
            for (int i = 0; i < 8; i++) {
                const int m = a_m0 + i * 16;
                pa[i] = *(const float4*)&A[(size_t)(row0 + m) * K + k0n + a_kq];
            }
#pragma unroll
            for (int i = 0; i < 4; i++) {
                const int n = b_n0 + i * 32;
                const size_t g = (size_t)(col0 + n) * K + k0n + b_kg;
                pbh[i] = *(const uint4*)&Bth[g];
                pbl[i] = *(const uint4*)&Btl[g];
            }
        }

        const uint32_t stAh = st, stAl = st + TILE_SZ;
        const uint32_t stBh = st + 2 * TILE_SZ, stBl = st + 3 * TILE_SZ;
#pragma unroll
        for (int ks = 0; ks < 4; ks++) {
            const uint32_t kbA = (uint32_t)(ks * 32) + a_kbb;
            const uint32_t kbB = (uint32_t)(ks * 32) + b_kbb;
            uint32_t ah[4][4], al[4][4], bh[2][4], bl[2][4];
#pragma unroll
            for (int i = 0; i < 4; i++) {
                ldsm4(stAh + a_rowoff[i] + (kbA ^ a_xor[i]), ah[i]);
                ldsm4(stAl + a_rowoff[i] + (kbA ^ a_xor[i]), al[i]);
            }
#pragma unroll
            for (int jp = 0; jp < 2; jp++) {
                ldsm4(stBh + b_rowoff[jp] + (kbB ^ b_xor[jp]), bh[jp]);
                ldsm4(stBl + b_rowoff[jp] + (kbB ^ b_xor[jp]), bl[jp]);
            }
#pragma unroll
            for (int i = 0; i < 4; i++)
#pragma unroll
                for (int j = 0; j < 4; j++)
                    mma16816(acc[i][j], ah[i], bh[j >> 1][(j & 1) * 2], bh[j >> 1][(j & 1) * 2 + 1]);
#pragma unroll
            for (int i = 0; i < 4; i++)
#pragma unroll
                for (int j = 0; j < 4; j++)
                    mma16816(acc[i][j], ah[i], bl[j >> 1][(j & 1) * 2], bl[j >> 1][(j & 1) * 2 + 1]);
#pragma unroll
            for (int i = 0; i < 4; i++)
#pragma unroll
                for (int j = 0; j < 4; j++)
                    mma16816(acc[i][j], al[i], bh[j >> 1][(j & 1) * 2], bh[j >> 1][(j & 1) * 2 + 1]);
        }
        __syncthreads();

        if (more) {
            const uint32_t stn = sb + (uint32_t)((c + 1) & 1) * STAGE_SZ;
#pragma unroll
            for (int i = 0; i < 8; i++) {
                __nv_bfloat16 h0, h1, h2, h3, l0, l1, l2, l3;
                split_bf16(pa[i].x, h0, l0); split_bf16(pa[i].y, h1, l1);
                split_bf16(pa[i].z, h2, l2); split_bf16(pa[i].w, h3, l3);
                asm volatile("st.shared.v2.b32 [%0], {%1, %2};"
                    :: "r"(stn + a_soff[i]), "r"(pack_bf16(h0, h1)), "r"(pack_bf16(h2, h3)) : "memory");
                asm volatile("st.shared.v2.b32 [%0], {%1, %2};"
                    :: "r"(stn + TILE_SZ + a_soff[i]), "r"(pack_bf16(l0, l1)), "r"(pack_bf16(l2, l3)) : "memory");
            }
#pragma unroll
            for (int i = 0; i < 4; i++) {
                asm volatile("st.shared.v4.b32 [%0], {%1, %2, %3, %4};"
                    :: "r"(stn + 2 * TILE_SZ + b_soff[i]), "r"(pbh[i].x), "r"(pbh[i].y), "r"(pbh[i].z), "r"(pbh[i].w) : "memory");
                asm volatile("st.shared.v4.b32 [%0], {%1, %2, %3, %4};"
                    :: "r"(stn + 3 * TILE_SZ + b_soff[i]), "r"(pbl[i].x), "r"(pbl[i].y), "r"(pbl[i].z), "r"(pbl[i].w) : "memory");
            }
            __syncthreads();
        }
    }

    // ---- epilogue ----
    const int cr  = lane >> 2;
    const int cc2 = (lane & 3) * 2;
#pragma unroll
    for (int i = 0; i < 4; i++) {
#pragma unroll
        for (int j = 0; j < 4; j++) {
            const int col  = wn + j * 8 + cc2;
            const int gcol = col0 + col;
            const int r0 = row0 + wm + i * 16 + cr;
            float v0 = acc[i][j][0] + sbias[col];
            float v1 = acc[i][j][1] + sbias[col + 1];
            float v2 = acc[i][j][2] + sbias[col];
            float v3 = acc[i][j][3] + sbias[col + 1];
            if (gcol < scale_cols) { v0 *= 0.125f; v1 *= 0.125f; v2 *= 0.125f; v3 *= 0.125f; }
            if (Ch) {
                uint32_t hp, lp;
                pack_split(v0, v1, hp, lp);
                *(uint32_t*)&Ch[(size_t)r0 * N + gcol] = hp;
                *(uint32_t*)&Cl[(size_t)r0 * N + gcol] = lp;
                pack_split(v2, v3, hp, lp);
                *(uint32_t*)&Ch[(size_t)(r0 + 8) * N + gcol] = hp;
                *(uint32_t*)&Cl[(size_t)(r0 + 8) * N + gcol] = lp;
            } else {
                *(float2*)&Cf[(size_t)r0 * N + gcol]       = make_float2(v0, v1);
                *(float2*)&Cf[(size_t)(r0 + 8) * N + gcol] = make_float2(v2, v3);
            }
        }
    }
}

// ============================================================================
// HMMA flash attention. CTA = 128 q-rows x (head, batch). 8 warps x 16 rows.
// Q/K/V pre-split bf16 hi/lo in gmem (Q pre-scaled by 0.125).
// QK: 3-term split HMMA. Softmax on fragments. PV: P split in registers,
// V via ldmatrix.trans, 3-term split HMMA.
// smem: Q(32K) + 2 stages x (Kh,Kl,Vh,Vl = 64K) = 160K.
// ============================================================================
#define ATT_SMEM (32768 + 2 * 65536)

__global__ __launch_bounds__(256, 1)
void attn_mma_kernel(const __nv_bfloat16* __restrict__ QKVh,
                     const __nv_bfloat16* __restrict__ QKVl,
                     float* __restrict__ out) {
    extern __shared__ char smem[];
    const uint32_t sb = smem_to_u32(smem);
    const int tid = threadIdx.x, wid = tid >> 5, lane = tid & 31;
    const int qt = blockIdx.x, h = blockIdx.y, b = blockIdx.z;
    const size_t rowbase = (size_t)b * S_LEN;
    const int hcol = h * HDIM;

    const uint32_t sQH = sb, sQL = sb + 16384;

    // producer assignment: 2 threads per 128B row, 4x16B chunks each
    const int p_r  = tid >> 1;
    const int p_cb = (tid & 1) * 64;

    // ---- Q (group 0, with first K/V) ----
    {
        const size_t grow = (rowbase + qt * 128 + p_r) * E3 + hcol;
#pragma unroll
        for (int i = 0; i < 4; i++) {
            const uint32_t bc  = (uint32_t)(p_cb + i * 16);
            const uint32_t off = (uint32_t)(p_r * 128) + (bc ^ (((uint32_t)p_r & 7) << 4));
            cp_async16(sQH + off, QKVh + grow + bc / 2);
            cp_async16(sQL + off, QKVl + grow + bc / 2);
        }
    }
    auto issue_kv = [&](int kt, int s) {
        const uint32_t st = sb + 32768 + (uint32_t)s * 65536;
        const size_t growK = (rowbase + kt * 128 + p_r) * E3 + (EMBED + hcol);
        const size_t growV = growK + EMBED;
#pragma unroll
        for (int i = 0; i < 4; i++) {
            const uint32_t bc  = (uint32_t)(p_cb + i * 16);
            const uint32_t off = (uint32_t)(p_r * 128) + (bc ^ (((uint32_t)p_r & 7) << 4));
            cp_async16(st + off,         QKVh + growK + bc / 2);
            cp_async16(st + 16384 + off, QKVl + growK + bc / 2);
            cp_async16(st + 32768 + off, QKVh + growV + bc / 2);
            cp_async16(st + 49152 + off, QKVl + growV + bc / 2);
        }
    };
    issue_kv(0, 0);
    CP_COMMIT();

    // ---- consumer address components ----
    const int wm = wid * 16;
    const int a_row = wm + (lane & 15);
    const uint32_t a_rowoff = (uint32_t)(a_row * 128);
    const uint32_t a_xor    = ((uint32_t)a_row & 7) << 4;
    const uint32_t a_kbb    = (uint32_t)((lane >> 4) * 16);
    const int b_nr = (lane & 7) | ((lane >> 4) << 3);
    const uint32_t b_kbb = (uint32_t)(((lane >> 3) & 1) * 16);
    const uint32_t b_xor = ((uint32_t)lane & 7) << 4;
    const int v_r = ((lane >> 3) & 1) * 8 + (lane & 7);
    const uint32_t v_cbb = (uint32_t)((lane >> 4) * 16);
    const uint32_t v_xor = ((uint32_t)lane & 7) << 4;

    float m0 = -1e30f, m1 = -1e30f, l0 = 0.f, l1 = 0.f;
    float o[8][4];
#pragma unroll
    for (int j = 0; j < 8; j++)
#pragma unroll
        for (int q = 0; q < 4; q++) o[j][q] = 0.f;

    for (int kt = 0; kt < S_LEN / 128; kt++) {
        const uint32_t st = sb + 32768 + (uint32_t)(kt & 1) * 65536;
        if (kt + 1 < S_LEN / 128) {
            issue_kv(kt + 1, (kt + 1) & 1);
            CP_COMMIT();
            asm volatile("cp.async.wait_group 1;" ::: "memory");
        } else {
            asm volatile("cp.async.wait_group 0;" ::: "memory");
        }
        __syncthreads();

        // === S = Q @ K^T (3-term split) ===
        float s[16][4];
#pragma unroll
        for (int j = 0; j < 16; j++)
#pragma unroll
            for (int q = 0; q < 4; q++) s[j][q] = 0.f;

#pragma unroll
        for (int ks = 0; ks < 4; ks++) {
            const uint32_t akb = (uint32_t)(ks * 32) + a_kbb;
            uint32_t ah[4], al[4];
            ldsm4(sQH + a_rowoff + (akb ^ a_xor), ah);
            ldsm4(sQL + a_rowoff + (akb ^ a_xor), al);
            const uint32_t kcb = ((uint32_t)(ks * 32) + b_kbb) ^ b_xor;
#pragma unroll
            for (int jp = 0; jp < 8; jp++) {
                const uint32_t roff = (uint32_t)((jp * 16 + b_nr) * 128);
                uint32_t kh[4], kl[4];
                ldsm4(st + roff + kcb, kh);
                ldsm4(st + 16384 + roff + kcb, kl);
                mma16816(s[2 * jp],     ah, kh[0], kh[1]);
                mma16816(s[2 * jp + 1], ah, kh[2], kh[3]);
                mma16816(s[2 * jp],     ah, kl[0], kl[1]);
                mma16816(s[2 * jp + 1], ah, kl[2], kl[3]);
                mma16816(s[2 * jp],     al, kh[0], kh[1]);
                mma16816(s[2 * jp + 1], al, kh[2], kh[3]);
            }
        }

        // === online softmax on fragments ===
        float mx0 = -1e30f, mx1 = -1e30f;
#pragma unroll
        for (int j = 0; j < 16; j++) {
            mx0 = fmaxf(mx0, fmaxf(s[j][0], s[j][1]));
            mx1 = fmaxf(mx1, fmaxf(s[j][2], s[j][3]));
        }
        mx0 = fmaxf(mx0, __shfl_xor_sync(0xffffffffu, mx0, 1));
        mx0 = fmaxf(mx0, __shfl_xor_sync(0xffffffffu, mx0, 2));
        mx1 = fmaxf(mx1, __shfl_xor_sync(0xffffffffu, mx1, 1));
        mx1 = fmaxf(mx1, __shfl_xor_sync(0xffffffffu, mx1, 2));
        const float mn0 = fmaxf(m0, mx0), mn1 = fmaxf(m1, mx1);
        const float al0 = __expf(m0 - mn0), al1 = __expf(m1 - mn1);
#pragma unroll
        for (int j = 0; j < 8; j++) {
            o[j][0] *= al0; o[j][1] *= al0;
            o[j][2] *= al1; o[j][3] *= al1;
        }
        float sum0 = 0.f, sum1 = 0.f;
#pragma unroll
        for (int j = 0; j < 16; j++) {
            s[j][0] = __expf(s[j][0] - mn0);
            s[j][1] = __expf(s[j][1] - mn0);
            s[j][2] = __expf(s[j][2] - mn1);
            s[j][3] = __expf(s[j][3] - mn1);
            sum0 += s[j][0] + s[j][1];
            sum1 += s[j][2] + s[j][3];
        }
        sum0 += __shfl_xor_sync(0xffffffffu, sum0, 1);
        sum0 += __shfl_xor_sync(0xffffffffu, sum0, 2);
        sum1 += __shfl_xor_sync(0xffffffffu, sum1, 1);
        sum1 += __shfl_xor_sync(0xffffffffu, sum1, 2);
        l0 = l0 * al0 + sum0;
        l1 = l1 * al1 + sum1;
        m0 = mn0; m1 = mn1;

        // === O += P @ V (3-term split, P from registers) ===
#pragma unroll
        for (int kk = 0; kk < 8; kk++) {
            uint32_t aph[4], apl[4];
            pack_split(s[2 * kk][0],     s[2 * kk][1],     aph[0], apl[0]);
            pack_split(s[2 * kk][2],     s[2 * kk][3],     aph[1], apl[1]);
            pack_split(s[2 * kk + 1][0], s[2 * kk + 1][1], aph[2], apl[2]);
            pack_split(s[2 * kk + 1][2], s[2 * kk + 1][3], aph[3], apl[3]);
            const uint32_t vroff = (uint32_t)((kk * 16 + v_r) * 128);
#pragma unroll
            for (int jn = 0; jn < 4; jn++) {
                const uint32_t vcb = ((uint32_t)(jn * 32) + v_cbb) ^ v_xor;
                uint32_t vh[4], vl[4];
                ldsm4t(st + 32768 + vroff + vcb, vh);
                ldsm4t(st + 49152 + vroff + vcb, vl);
                mma16816(o[2 * jn],     aph, vh[0], vh[1]);
                mma16816(o[2 * jn + 1], aph, vh[2], vh[3]);
                mma16816(o[2 * jn],     aph, vl[0], vl[1]);
                mma16816(o[2 * jn + 1], aph, vl[2], vl[3]);
                mma16816(o[2 * jn],     apl, vh[0], vh[1]);
                mma16816(o[2 * jn + 1], apl, vh[2], vh[3]);
            }
        }
        __syncthreads();   // all reads of this stage done before it is refilled
    }

    // === epilogue: normalize, write [B,S,E] with head offset ===
    const int gr  = lane >> 2;
    const int cc2 = (lane & 3) * 2;
    const float inv0 = 1.f / l0, inv1 = 1.f / l1;
    const size_t r0 = rowbase + (size_t)(qt * 128 + wm + gr);
#pragma unroll
    for (int j = 0; j < 8; j++) {
        const int col = hcol + j * 8 + cc2;
        *(float2*)&out[r0 * EMBED + col] =
            make_float2(o[j][0] * inv0, o[j][1] * inv0);
        *(float2*)&out[(r0 + 8) * EMBED + col] =
            make_float2(o[j][2] * inv1, o[j][3] * inv1);
    }
}

// ============================================================================
// Launch
// ============================================================================
extern "C" void kernel_launch(void* const* d_in, const int* in_sizes, int n_in,
                              void* d_out, int out_size) {
    const float* x     = (const float*)d_in[0];
    const float* W_qkv = (const float*)d_in[1];
    const float* b_qkv = (const float*)d_in[2];
    const float* W_out = (const float*)d_in[3];
    const float* b_out = (const float*)d_in[4];
    float* out = (float*)d_out;

    float* attn_ptr;
    cudaGetSymbolAddress((void**)&attn_ptr, g_attn);
    __nv_bfloat16 *qkvh, *qkvl, *wq_hi, *wq_lo, *wo_hi, *wo_lo;
    cudaGetSymbolAddress((void**)&qkvh, g_qkvh);
    cudaGetSymbolAddress((void**)&qkvl, g_qkvl);
    cudaGetSymbolAddress((void**)&wq_hi, g_wq_hi);
    cudaGetSymbolAddress((void**)&wq_lo, g_wq_lo);
    cudaGetSymbolAddress((void**)&wo_hi, g_wo_hi);
    cudaGetSymbolAddress((void**)&wo_lo, g_wo_lo);

    cudaFuncSetAttribute(tc_gemm_bias, cudaFuncAttributeMaxDynamicSharedMemorySize, SM_GEMM_TOTAL);
    cudaFuncSetAttribute(attn_mma_kernel, cudaFuncAttributeMaxDynamicSharedMemorySize, ATT_SMEM);

    // 0) weight transpose + bf16 split
    wtrans_split_kernel<<<dim3(E3 / 32, EMBED / 32), 256>>>(W_qkv, wq_hi, wq_lo, EMBED, E3);
    wtrans_split_kernel<<<dim3(EMBED / 32, EMBED / 32), 256>>>(W_out, wo_hi, wo_lo, EMBED, EMBED);

    // 1) QKV projection -> pre-split bf16 hi/lo, Q columns pre-scaled by 0.125
    tc_gemm_bias<<<dim3(E3 / BN, M_TOTAL / BM), 256, SM_GEMM_TOTAL>>>(
        x, wq_hi, wq_lo, b_qkv, nullptr, qkvh, qkvl, M_TOTAL, E3, EMBED, EMBED);

    // 2) Attention (HMMA flash)
    dim3 g2(S_LEN / 128, HEADS, BATCH);
    attn_mma_kernel<<<g2, 256, ATT_SMEM>>>(qkvh, qkvl, attn_ptr);

    // 3) Output projection -> fp32 final output
    tc_gemm_bias<<<dim3(EMBED / BN, M_TOTAL / BM), 256, SM_GEMM_TOTAL>>>(
        attn_ptr, wo_hi, wo_lo, b_out, out, nullptr, nullptr, M_TOTAL, EMBED, EMBED, 0);
}